// round 2
// baseline (speedup 1.0000x reference)
#include <cuda_runtime.h>
#include <cstdint>

// Problem constants (fixed shapes per reference)
#define C_   64
#define D_   8
#define K15_ 15
#define K16_ 16
#define OUTW 512
#define MAXB 32768

// Scratch (no cudaMalloc allowed): zero-initialized device globals.
__device__ uint8_t        g_table[1 << K15_];      // 32 KB: 15-bit sign pattern -> argmax_j (s@H)
__device__ unsigned short g_woff[MAXB * C_];        // 4 MB: per (b,c) smem word-offset = (c*16+idx)*32

// ---------------------------------------------------------------------------
// Kernel T: precompute argmax table. h[j] = sum_k (+-1)*H[k,j]; first-max via strict >.
// ---------------------------------------------------------------------------
__global__ void table_kernel(const float* __restrict__ H) {
    int m = blockIdx.x * blockDim.x + threadIdx.x;
    if (m >= (1 << K15_)) return;
    float h[K16_];
#pragma unroll
    for (int j = 0; j < K16_; j++) h[j] = 0.f;
#pragma unroll
    for (int k = 0; k < K15_; k++) {
        float sgn = ((m >> k) & 1) ? 1.f : -1.f;
#pragma unroll
        for (int j = 0; j < K16_; j++) h[j] += sgn * H[k * K16_ + j];
    }
    float best = h[0];
    int   bi   = 0;
#pragma unroll
    for (int j = 1; j < K16_; j++)
        if (h[j] > best) { best = h[j]; bi = j; }
    g_table[m] = (uint8_t)bi;
}

// ---------------------------------------------------------------------------
// Kernel 1: per (b,c) compute sign pattern of x[b,c,:]@S[c] - T[c], look up argmax,
// store precomputed smem word offset. Block = 256 thr = 8 warps, handles 32 b.
// Warp w owns c in [8w, 8w+8); lane = b_local. S/T reads are warp-broadcast LDS;
// x staged in smem with +1 padding (row stride 513) for conflict-free lane-strided reads.
// ---------------------------------------------------------------------------
__global__ void __launch_bounds__(256) idx_kernel(const float* __restrict__ x,
                                                  const float* __restrict__ S,
                                                  const float* __restrict__ T,
                                                  int B) {
    extern __shared__ float sm[];
    float* x_s = sm;                       // 32 * 513 floats
    float* S_s = sm + 32 * 513;            // 64*8*15 = 7680 floats, layout [c][d][k]
    float* T_s = S_s + C_ * D_ * K15_;     // 64*15 floats

    const int tid = threadIdx.x;
    const int b0  = blockIdx.x * 32;

    // Stage x rows (coalesced), S, T
    for (int i = tid; i < 32 * 512; i += 256) {
        int bl = i >> 9, col = i & 511;
        float v = 0.f;
        if (b0 + bl < B) v = x[(size_t)(b0 + bl) * 512 + col];
        x_s[bl * 513 + col] = v;
    }
    for (int i = tid; i < C_ * D_ * K15_; i += 256) S_s[i] = S[i];
    for (int i = tid; i < C_ * K15_; i += 256)      T_s[i] = T[i];
    __syncthreads();

    const int warp = tid >> 5, lane = tid & 31;
    const int b = b0 + lane;

#pragma unroll
    for (int cc = 0; cc < 8; cc++) {
        const int c = warp * 8 + cc;
        float xr[D_];
#pragma unroll
        for (int d = 0; d < D_; d++) xr[d] = x_s[lane * 513 + c * D_ + d];
        float acc[K15_];
#pragma unroll
        for (int k = 0; k < K15_; k++) acc[k] = 0.f;
#pragma unroll
        for (int d = 0; d < D_; d++) {
            const float xd = xr[d];
#pragma unroll
            for (int k = 0; k < K15_; k++)
                acc[k] += xd * S_s[(c * D_ + d) * K15_ + k];   // broadcast LDS
        }
        unsigned m = 0;
#pragma unroll
        for (int k = 0; k < K15_; k++)
            if (acc[k] > T_s[c * K15_ + k]) m |= (1u << k);     // p > 0  <=>  dot > T
        const int idx = g_table[m];
        if (b < B)
            g_woff[(size_t)b * C_ + c] = (unsigned short)((c * K16_ + idx) * 32);
    }
}

// ---------------------------------------------------------------------------
// Kernel 2: out[b, j0+lane] = sum_c LUT[c, idx[b,c], j0+lane] via smem-tiled LUT.
// Grid: (16 j-tiles of 32) x (B/512). Block = 512 thr = 16 warps; warp w owns one b
// per round; lane = j within tile. LUT tile 64*16*32 f32 = 128 KB smem (1 CTA/SM).
// Offsets staged per round as byte offsets -> inner loop is LDS(off)+IADD+LDS+FADD.
// ---------------------------------------------------------------------------
__global__ void __launch_bounds__(512) sum_kernel(const float* __restrict__ LUT,
                                                  float* __restrict__ out,
                                                  int B, int bpb) {
    extern __shared__ float sm[];
    float*    tile = sm;                                    // 32768 floats
    unsigned* offs = (unsigned*)(sm + C_ * K16_ * 32);      // 16*64 uint32 byte offsets

    const int tid  = threadIdx.x;
    const int j0   = blockIdx.x * 32;

    // Stage LUT j-slice: row = c*16+e, 32 consecutive j per row (coalesced 128B).
    for (int i = tid; i < C_ * K16_ * 32; i += 512) {
        int row = i >> 5, j = i & 31;
        tile[i] = LUT[(size_t)row * OUTW + j0 + j];
    }

    const int warp = tid >> 5, lane = tid & 31;
    const int bbase = blockIdx.y * bpb;
    const char* tilec = (const char*)tile;

    for (int bb = 0; bb < bpb; bb += 16) {
        __syncthreads();   // first iter: tile ready; later: offs reuse safe
        const int b0 = bbase + bb;
        {
            // 16 b * 64 offsets = 1024 u16 = 512 u32, one per thread (coalesced)
            const unsigned v = ((const unsigned*)(g_woff + (size_t)b0 * C_))[tid];
            offs[2 * tid]     = (v & 0xFFFFu) * 4u;
            offs[2 * tid + 1] = (v >> 16) * 4u;
        }
        __syncthreads();

        const int b = b0 + warp;
        const unsigned* myoffs = offs + warp * C_;
        const char* lanep = tilec + lane * 4;
        float acc = 0.f;
#pragma unroll
        for (int c = 0; c < C_; c++) {
            const unsigned off = myoffs[c];                  // broadcast LDS, imm offset
            acc += *(const float*)(lanep + off);             // conflict-free gather
        }
        if (b < B) out[(size_t)b * OUTW + j0 + lane] = acc;  // coalesced 128B store
    }
}

// ---------------------------------------------------------------------------
extern "C" void kernel_launch(void* const* d_in, const int* in_sizes, int n_in,
                              void* d_out, int out_size) {
    const float* x   = (const float*)d_in[0];
    const float* S   = (const float*)d_in[1];
    const float* H   = (const float*)d_in[2];
    const float* T   = (const float*)d_in[3];
    const float* LUT = (const float*)d_in[4];
    float*       out = (float*)d_out;

    const int B = in_sizes[0] / (C_ * D_);

    // 1) argmax table from H
    table_kernel<<<(1 << K15_) / 256, 256>>>(H);

    // 2) sign patterns -> smem word offsets
    size_t sm1 = (size_t)(32 * 513 + C_ * D_ * K15_ + C_ * K15_) * sizeof(float);
    cudaFuncSetAttribute(idx_kernel, cudaFuncAttributeMaxDynamicSharedMemorySize, (int)sm1);
    idx_kernel<<<(B + 31) / 32, 256, sm1>>>(x, S, T, B);

    // 3) tiled gather-sum
    size_t sm2 = (size_t)C_ * K16_ * 32 * sizeof(float) + 16 * C_ * sizeof(unsigned);
    cudaFuncSetAttribute(sum_kernel, cudaFuncAttributeMaxDynamicSharedMemorySize, (int)sm2);
    const int bpb = 512;                       // b per block -> LUT reload amortized (128 MB L2 total)
    dim3 g2(OUTW / 32, (B + bpb - 1) / bpb);
    sum_kernel<<<g2, 512, sm2>>>(LUT, out, B, bpb);
}

// round 5
// speedup vs baseline: 2.5012x; 2.5012x over previous
#include <cuda_runtime.h>
#include <cuda_fp16.h>
#include <cstdint>

// Problem constants (fixed shapes per reference)
#define C_    64
#define D_    8
#define K15_  15
#define K16_  16
#define OUTW  512
#define MAXB  32768
#define NPAIR 32          // C_/2
#define NROWS 8192        // NPAIR*256
#define NJT   64          // OUTW/8 j-tiles
#define JT_W  8           // j per tile
#define BCHUNK 4096

// Scratch (no cudaMalloc allowed): zero-initialized device globals.
__device__ uint8_t        g_table[1 << K15_];          // 32 KB: sign pattern -> argmax_j
__device__ unsigned short g_poff[MAXB * NPAIR];        // 2 MB: (b,p) -> row id p*256+e1*16+e2
__device__ __half         g_lut2[NJT * NROWS * JT_W];  // 8 MB: paired LUT, [jt][row][jj] fp16

// ---------------------------------------------------------------------------
// Kernel T: precompute argmax table. h[j] = sum_k (+-1)*H[k,j]; first-max via strict >.
// ---------------------------------------------------------------------------
__global__ void table_kernel(const float* __restrict__ H) {
    int m = blockIdx.x * blockDim.x + threadIdx.x;
    if (m >= (1 << K15_)) return;
    float h[K16_];
#pragma unroll
    for (int j = 0; j < K16_; j++) h[j] = 0.f;
#pragma unroll
    for (int k = 0; k < K15_; k++) {
        float sgn = ((m >> k) & 1) ? 1.f : -1.f;
#pragma unroll
        for (int j = 0; j < K16_; j++) h[j] += sgn * H[k * K16_ + j];
    }
    float best = h[0];
    int   bi = 0;
#pragma unroll
    for (int j = 1; j < K16_; j++)
        if (h[j] > best) { best = h[j]; bi = j; }
    g_table[m] = (uint8_t)bi;
}

// ---------------------------------------------------------------------------
// Kernel 1: per (b,c) sign pattern -> argmax lookup; emit per-PAIR row id.
// Warp w owns c in [8w, 8w+8) (=> pairs 4w..4w+3 entirely in-lane); lane = b_local.
// Identical dot/sign math to the 553us passing kernel.
// ---------------------------------------------------------------------------
__global__ void __launch_bounds__(256) idx_kernel(const float* __restrict__ x,
                                                  const float* __restrict__ S,
                                                  const float* __restrict__ T,
                                                  int B) {
    extern __shared__ float sm[];
    float* x_s = sm;                       // 32 * 513
    float* S_s = sm + 32 * 513;            // [c][d][k]
    float* T_s = S_s + C_ * D_ * K15_;

    const int tid = threadIdx.x;
    const int b0 = blockIdx.x * 32;

    for (int i = tid; i < 32 * 512; i += 256) {
        int bl = i >> 9, col = i & 511;
        float v = 0.f;
        if (b0 + bl < B) v = x[(size_t)(b0 + bl) * 512 + col];
        x_s[bl * 513 + col] = v;
    }
    for (int i = tid; i < C_ * D_ * K15_; i += 256) S_s[i] = S[i];
    for (int i = tid; i < C_ * K15_; i += 256)      T_s[i] = T[i];
    __syncthreads();

    const int warp = tid >> 5, lane = tid & 31;
    const int b = b0 + lane;

    int e8[8];
#pragma unroll
    for (int cc = 0; cc < 8; cc++) {
        const int c = warp * 8 + cc;
        float xr[D_];
#pragma unroll
        for (int d = 0; d < D_; d++) xr[d] = x_s[lane * 513 + c * D_ + d];
        float acc[K15_];
#pragma unroll
        for (int k = 0; k < K15_; k++) acc[k] = 0.f;
#pragma unroll
        for (int d = 0; d < D_; d++) {
            const float xd = xr[d];
#pragma unroll
            for (int k = 0; k < K15_; k++)
                acc[k] += xd * S_s[(c * D_ + d) * K15_ + k];
        }
        unsigned m = 0;
#pragma unroll
        for (int k = 0; k < K15_; k++)
            if (acc[k] > T_s[c * K15_ + k]) m |= (1u << k);
        e8[cc] = g_table[m];
    }

    if (b < B) {
        ushort4 v;
        v.x = (unsigned short)((4 * warp + 0) * 256 + e8[0] * 16 + e8[1]);
        v.y = (unsigned short)((4 * warp + 1) * 256 + e8[2] * 16 + e8[3]);
        v.z = (unsigned short)((4 * warp + 2) * 256 + e8[4] * 16 + e8[5]);
        v.w = (unsigned short)((4 * warp + 3) * 256 + e8[6] * 16 + e8[7]);
        *(ushort4*)(g_poff + (size_t)b * NPAIR + 4 * warp) = v;   // 8B aligned store
    }
}

// ---------------------------------------------------------------------------
// Kernel 2 (build): LUT2[p][e1*16+e2][j] = LUT[2p*16+e1][j] + LUT[(2p+1)*16+e2][j]
// stored fp16 in [jt][row][jj] order so a 16B LDS.128 later fetches one row's 8 j.
// grid = NROWS blocks x 64 threads (thread = j-tile); reads fully coalesced.
// ---------------------------------------------------------------------------
__global__ void __launch_bounds__(64) build_kernel(const float* __restrict__ LUT) {
    const int row = blockIdx.x;           // p*256 + e1*16 + e2
    const int t   = threadIdx.x;          // j-tile
    const int p = row >> 8, e = row & 255;
    const int r0 = p * 32 + (e >> 4);
    const int r1 = p * 32 + 16 + (e & 15);
    const float4* a = (const float4*)(LUT + (size_t)r0 * OUTW + t * 8);
    const float4* c = (const float4*)(LUT + (size_t)r1 * OUTW + t * 8);
    const float4 a0 = a[0], a1 = a[1], c0 = c[0], c1 = c[1];
    __half2 h0 = __floats2half2_rn(a0.x + c0.x, a0.y + c0.y);
    __half2 h1 = __floats2half2_rn(a0.z + c0.z, a0.w + c0.w);
    __half2 h2 = __floats2half2_rn(a1.x + c1.x, a1.y + c1.y);
    __half2 h3 = __floats2half2_rn(a1.z + c1.z, a1.w + c1.w);
    uint4 v;
    v.x = *(uint32_t*)&h0; v.y = *(uint32_t*)&h1;
    v.z = *(uint32_t*)&h2; v.w = *(uint32_t*)&h3;
    *(uint4*)((char*)g_lut2 + ((size_t)t * NROWS + row) * 16) = v;
}

// ---------------------------------------------------------------------------
// Kernel 3 (gather): out[b, jt*8+jj] = sum_p LUT2[jt][poff[b,p]][jj]
// CTA: 1024 thr, smem = 128KB tile (one jt slice: 8192 rows x 16B).
// Thread = one b per round; 32 random-row LDS.128 gathers, level-1 sums in
// fp16 (HADD2), remaining 16-term accumulation in fp32.
// Grid: (64 jt) x (B/4096 b-chunks) = 512 CTAs, 1 CTA/SM.
// ---------------------------------------------------------------------------
__device__ __forceinline__ void acc_pairword(const char* smem, uint32_t w, float2 acc[4]) {
    const uint4 ra = *(const uint4*)(smem + ((w & 0xFFFFu) << 4));
    const uint4 rb = *(const uint4*)(smem + ((w >> 16) << 4));
    const __half2* ha = (const __half2*)&ra;
    const __half2* hb = (const __half2*)&rb;
#pragma unroll
    for (int q = 0; q < 4; q++) {
        const float2 f = __half22float2(__hadd2(ha[q], hb[q]));
        acc[q].x += f.x;
        acc[q].y += f.y;
    }
}

__global__ void __launch_bounds__(1024) gather_kernel(float* __restrict__ out, int B) {
    extern __shared__ char smem[];        // 131072 B tile
    const int jt  = blockIdx.x;
    const int tid = threadIdx.x;

    // Stage this jt's LUT2 slice: 8192 rows x 16B, contiguous in global.
    {
        const uint4* src = (const uint4*)((const char*)g_lut2 + (size_t)jt * (NROWS * 16));
        uint4* dst = (uint4*)smem;
#pragma unroll
        for (int i = 0; i < 8; i++) dst[tid + i * 1024] = src[tid + i * 1024];
    }
    __syncthreads();

    const int b0 = blockIdx.y * BCHUNK;
#pragma unroll
    for (int bb = 0; bb < BCHUNK / 1024; bb++) {
        const int b  = b0 + bb * 1024 + tid;
        const int bc = (b < B) ? b : (B - 1);
        const uint4* op = (const uint4*)(g_poff + (size_t)bc * NPAIR);  // 64B of row ids
        const uint4 o0 = op[0], o1 = op[1], o2 = op[2], o3 = op[3];

        float2 acc[4];
#pragma unroll
        for (int q = 0; q < 4; q++) acc[q] = make_float2(0.f, 0.f);

        acc_pairword(smem, o0.x, acc); acc_pairword(smem, o0.y, acc);
        acc_pairword(smem, o0.z, acc); acc_pairword(smem, o0.w, acc);
        acc_pairword(smem, o1.x, acc); acc_pairword(smem, o1.y, acc);
        acc_pairword(smem, o1.z, acc); acc_pairword(smem, o1.w, acc);
        acc_pairword(smem, o2.x, acc); acc_pairword(smem, o2.y, acc);
        acc_pairword(smem, o2.z, acc); acc_pairword(smem, o2.w, acc);
        acc_pairword(smem, o3.x, acc); acc_pairword(smem, o3.y, acc);
        acc_pairword(smem, o3.z, acc); acc_pairword(smem, o3.w, acc);

        if (b < B) {
            float4* orow = (float4*)(out + (size_t)b * OUTW + jt * JT_W);
            orow[0] = make_float4(acc[0].x, acc[0].y, acc[1].x, acc[1].y);
            orow[1] = make_float4(acc[2].x, acc[2].y, acc[3].x, acc[3].y);
        }
    }
}

// ---------------------------------------------------------------------------
extern "C" void kernel_launch(void* const* d_in, const int* in_sizes, int n_in,
                              void* d_out, int out_size) {
    const float* x   = (const float*)d_in[0];
    const float* S   = (const float*)d_in[1];
    const float* H   = (const float*)d_in[2];
    const float* T   = (const float*)d_in[3];
    const float* LUT = (const float*)d_in[4];
    float*       out = (float*)d_out;

    const int B = in_sizes[0] / (C_ * D_);

    // 1) argmax table from H
    table_kernel<<<(1 << K15_) / 256, 256>>>(H);

    // 2) sign patterns -> per-pair row ids
    size_t sm1 = (size_t)(32 * 513 + C_ * D_ * K15_ + C_ * K15_) * sizeof(float);
    cudaFuncSetAttribute(idx_kernel, cudaFuncAttributeMaxDynamicSharedMemorySize, (int)sm1);
    idx_kernel<<<(B + 31) / 32, 256, sm1>>>(x, S, T, B);

    // 3) paired fp16 LUT2 in gather-friendly layout
    build_kernel<<<NROWS, 64>>>(LUT);

    // 4) tiled pair-gather sum
    const int smg = NROWS * 16;   // 128 KB
    cudaFuncSetAttribute(gather_kernel, cudaFuncAttributeMaxDynamicSharedMemorySize, smg);
    dim3 gg(NJT, (B + BCHUNK - 1) / BCHUNK);
    gather_kernel<<<gg, 1024, smg>>>(out, B);
}

// round 7
// speedup vs baseline: 2.9310x; 1.1718x over previous
#include <cuda_runtime.h>
#include <cuda_fp16.h>
#include <cstdint>

// Problem constants (fixed shapes per reference)
#define C_    64
#define D_    8
#define K15_  15
#define K16_  16
#define OUTW  512
#define MAXB  32768
#define NPAIR 32          // C_/2
#define NROWS 8192        // NPAIR*256
#define NPG   16          // pair-groups (2 pairs each)
#define NJT   8           // j-tiles of 64
#define GCHUNK 512        // b per gather CTA

// Scratch (no cudaMalloc allowed): zero-initialized device globals.
__device__ uint8_t        g_table[1 << K15_];      // 32 KB: sign pattern -> argmax_j
__device__ unsigned short g_poff[MAXB * NPAIR];    // 2 MB: (b,p) -> scaled local byte offset
__device__ __half         g_lut2[NROWS * OUTW];    // 8 MB: paired LUT rows [row=p*256+e][j=512] fp16

__device__ __forceinline__ void cp16(uint32_t daddr, const void* src) {
    asm volatile("cp.async.cg.shared.global [%0], [%1], 16;" :: "r"(daddr), "l"(src) : "memory");
}

// ---------------------------------------------------------------------------
// Kernel T: precompute argmax table (H staged in smem).
// ---------------------------------------------------------------------------
__global__ void __launch_bounds__(256) table_kernel(const float* __restrict__ H) {
    __shared__ float Hs[K15_ * K16_];
    for (int i = threadIdx.x; i < K15_ * K16_; i += 256) Hs[i] = H[i];
    __syncthreads();
    int m = blockIdx.x * blockDim.x + threadIdx.x;
    if (m >= (1 << K15_)) return;
    float h[K16_];
#pragma unroll
    for (int j = 0; j < K16_; j++) h[j] = 0.f;
#pragma unroll
    for (int k = 0; k < K15_; k++) {
        float sgn = ((m >> k) & 1) ? 1.f : -1.f;
#pragma unroll
        for (int j = 0; j < K16_; j++) h[j] += sgn * Hs[k * K16_ + j];
    }
    float best = h[0];
    int   bi = 0;
#pragma unroll
    for (int j = 1; j < K16_; j++)
        if (h[j] > best) { best = h[j]; bi = j; }
    g_table[m] = (uint8_t)bi;
}

// ---------------------------------------------------------------------------
// Kernel 1: per (b,c) sign pattern -> argmax; emit per-pair scaled byte offsets.
// Warp w owns c in [8w, 8w+8) (pairs 4w..4w+3); lane = b_local.
// S staged padded [c][d][16] for float4 broadcast loads; x stride 516 for
// conflict-free per-lane float4 loads. Same dot/sign math as passing kernel.
// ---------------------------------------------------------------------------
#define XSTR 516
__global__ void __launch_bounds__(256) idx_kernel(const float* __restrict__ x,
                                                  const float* __restrict__ S,
                                                  const float* __restrict__ T,
                                                  int B) {
    extern __shared__ float sm[];
    float* x_s = sm;                         // 32 * 516
    float* S_s = sm + 32 * XSTR;             // [c][d][16] = 8192
    float* T_s = S_s + C_ * D_ * 16;         // [c][15] = 960

    const int tid = threadIdx.x;
    const int b0 = blockIdx.x * 32;

    // Stage x via float4 (coalesced)
    for (int i = tid; i < 32 * 128; i += 256) {
        int bl = i >> 7, col4 = i & 127;
        float4 v = make_float4(0.f, 0.f, 0.f, 0.f);
        if (b0 + bl < B) v = ((const float4*)x)[(size_t)(b0 + bl) * 128 + col4];
        *(float4*)(x_s + bl * XSTR + col4 * 4) = v;
    }
    // Stage S padded to k-stride 16
    for (int i = tid; i < C_ * D_ * K15_; i += 256) {
        int cd = i / K15_, k = i - cd * K15_;
        S_s[cd * 16 + k] = S[i];
    }
    for (int i = tid; i < C_ * K15_; i += 256) T_s[i] = T[i];
    __syncthreads();

    const int warp = tid >> 5, lane = tid & 31;
    const int b = b0 + lane;

    int e8[8];
#pragma unroll
    for (int cc = 0; cc < 8; cc++) {
        const int c = warp * 8 + cc;
        const float4 xa = *(const float4*)(x_s + lane * XSTR + c * 8);
        const float4 xb = *(const float4*)(x_s + lane * XSTR + c * 8 + 4);
        float xr[D_] = {xa.x, xa.y, xa.z, xa.w, xb.x, xb.y, xb.z, xb.w};
        float acc[16];
#pragma unroll
        for (int k = 0; k < 16; k++) acc[k] = 0.f;
#pragma unroll
        for (int d = 0; d < D_; d++) {
            const float xd = xr[d];
            const float4* s4 = (const float4*)(S_s + (c * D_ + d) * 16);
            const float4 s0 = s4[0], s1 = s4[1], s2 = s4[2], s3 = s4[3];
            acc[0]  += xd * s0.x; acc[1]  += xd * s0.y; acc[2]  += xd * s0.z; acc[3]  += xd * s0.w;
            acc[4]  += xd * s1.x; acc[5]  += xd * s1.y; acc[6]  += xd * s1.z; acc[7]  += xd * s1.w;
            acc[8]  += xd * s2.x; acc[9]  += xd * s2.y; acc[10] += xd * s2.z; acc[11] += xd * s2.w;
            acc[12] += xd * s3.x; acc[13] += xd * s3.y; acc[14] += xd * s3.z;
        }
        unsigned m = 0;
#pragma unroll
        for (int k = 0; k < K15_; k++)
            if (acc[k] > T_s[c * K15_ + k]) m |= (1u << k);
        e8[cc] = g_table[m];
    }

    if (b < B) {
        // pair p = 4*warp + t; e = e1*16+e2; scaled offset = ((p&1)<<15) | (e<<7)
        ushort4 v;
        v.x = (unsigned short)(((e8[0] * 16 + e8[1]) << 7));
        v.y = (unsigned short)((1 << 15) | ((e8[2] * 16 + e8[3]) << 7));
        v.z = (unsigned short)(((e8[4] * 16 + e8[5]) << 7));
        v.w = (unsigned short)((1 << 15) | ((e8[6] * 16 + e8[7]) << 7));
        *(ushort4*)(g_poff + (size_t)b * NPAIR + 4 * warp) = v;
    }
}

// ---------------------------------------------------------------------------
// Kernel 2 (build): LUT2 row (p*256 + e1*16+e2) = LUT[2p*16+e1][:] + LUT[(2p+1)*16+e2][:]
// fp16, row-major [row][512 j] (1 KB rows). Fully coalesced.
// ---------------------------------------------------------------------------
__global__ void __launch_bounds__(64) build_kernel(const float* __restrict__ LUT) {
    const int row = blockIdx.x;           // p*256 + e1*16 + e2
    const int t   = threadIdx.x;          // 64 threads, 8 j each
    const int p = row >> 8, e = row & 255;
    const int r0 = p * 32 + (e >> 4);
    const int r1 = p * 32 + 16 + (e & 15);
    const float4* a = (const float4*)(LUT + (size_t)r0 * OUTW + t * 8);
    const float4* c = (const float4*)(LUT + (size_t)r1 * OUTW + t * 8);
    const float4 a0 = a[0], a1 = a[1], c0 = c[0], c1 = c[1];
    __half2 h0 = __floats2half2_rn(a0.x + c0.x, a0.y + c0.y);
    __half2 h1 = __floats2half2_rn(a0.z + c0.z, a0.w + c0.w);
    __half2 h2 = __floats2half2_rn(a1.x + c1.x, a1.y + c1.y);
    __half2 h3 = __floats2half2_rn(a1.z + c1.z, a1.w + c1.w);
    uint4 v;
    v.x = *(uint32_t*)&h0; v.y = *(uint32_t*)&h1;
    v.z = *(uint32_t*)&h2; v.w = *(uint32_t*)&h3;
    *(uint4*)((char*)g_lut2 + ((size_t)row * OUTW + t * 8) * 2) = v;
}

// ---------------------------------------------------------------------------
// Kernel 3 (gather): out[b, jt*64 + 2*lane..] = sum_p LUT2[row(b,p)][j-slice]
// CTA: 512 thr / 16 warps; warp owns 32 b; lane owns 2 j. 16 pair-group tiles
// (512 rows x 128 B = 64 KB) double-buffered via cp.async; all-lane broadcast
// row reads -> conflict-free LDS.32. Accumulators live in registers across pgs.
// smem: ids 32 KB @0, buf0 @32768, buf1 @98304  (160 KB total).
// ---------------------------------------------------------------------------
#define IDS_BYTES (GCHUNK * 64)
#define BUF0 32768
#define BUF1 98304
#define GSMEM (BUF1 + 65536)

__global__ void __launch_bounds__(512) gather_kernel(float* __restrict__ out, int B) {
    extern __shared__ char smem[];
    uint32_t* ids_s = (uint32_t*)smem;                 // [512 b][16 u32]
    const int tid = threadIdx.x, w = tid >> 5, lane = tid & 31;
    const int jt = blockIdx.x;
    const int chunk = blockIdx.y * GCHUNK;

    const char* lut_base = (const char*)g_lut2 + (size_t)jt * 128;
    const uint32_t smem_base = (uint32_t)__cvta_generic_to_shared(smem);

    // ---- prefetch pg 0 into buf0
    {
        const char* src = lut_base;                    // rows 0.., stride 1024 B
#pragma unroll
        for (int k = 0; k < 8; k++) {
            int lin = k * 512 + tid;
            int r = lin >> 3, seg = lin & 7;
            cp16(smem_base + BUF0 + r * 128 + seg * 16, src + (size_t)r * 1024 + seg * 16);
        }
        asm volatile("cp.async.commit_group;" ::: "memory");
    }

    // ---- stage ids (64 B per b), clamped
    for (int i = tid; i < GCHUNK * 4; i += 512) {
        int bl = i >> 2;
        int bc = chunk + bl; if (bc >= B) bc = B - 1;
        ((uint4*)ids_s)[i] = *((const uint4*)(g_poff + (size_t)bc * NPAIR) + (i & 3));
    }

    float2 acc[32];
#pragma unroll
    for (int i = 0; i < 32; i++) acc[i] = make_float2(0.f, 0.f);

    const uint32_t* myids = ids_s + (w * 32) * NPG;

    for (int pg = 0; pg < NPG; pg++) {
        const uint32_t buf = (pg & 1) ? BUF1 : BUF0;
        if (pg + 1 < NPG) {
            const uint32_t nbuf = (pg & 1) ? BUF0 : BUF1;
            const char* src = lut_base + (size_t)(pg + 1) * 512 * 1024;
#pragma unroll
            for (int k = 0; k < 8; k++) {
                int lin = k * 512 + tid;
                int r = lin >> 3, seg = lin & 7;
                cp16(smem_base + nbuf + r * 128 + seg * 16, src + (size_t)r * 1024 + seg * 16);
            }
            asm volatile("cp.async.commit_group;" ::: "memory");
            asm volatile("cp.async.wait_group 1;" ::: "memory");
        } else {
            asm volatile("cp.async.wait_group 0;" ::: "memory");
        }
        __syncthreads();

        const char* bufl = smem + buf + lane * 4;
#pragma unroll
        for (int i = 0; i < 32; i++) {
            const uint32_t idw = myids[i * NPG + pg];          // broadcast LDS
            const __half2 v0 = *(const __half2*)(bufl + (idw & 0xFFFFu));
            const __half2 v1 = *(const __half2*)(bufl + (idw >> 16));
            const float2 f = __half22float2(__hadd2(v0, v1));
            acc[i].x += f.x;
            acc[i].y += f.y;
        }
        __syncthreads();   // protect buffer reuse by next prefetch
    }

#pragma unroll
    for (int i = 0; i < 32; i++) {
        const int b = chunk + w * 32 + i;
        if (b < B)
            *(float2*)(out + (size_t)b * OUTW + jt * 64 + lane * 2) = acc[i];
    }
}

// ---------------------------------------------------------------------------
extern "C" void kernel_launch(void* const* d_in, const int* in_sizes, int n_in,
                              void* d_out, int out_size) {
    const float* x   = (const float*)d_in[0];
    const float* S   = (const float*)d_in[1];
    const float* H   = (const float*)d_in[2];
    const float* T   = (const float*)d_in[3];
    const float* LUT = (const float*)d_in[4];
    float*       out = (float*)d_out;

    const int B = in_sizes[0] / (C_ * D_);

    // 1) argmax table from H
    table_kernel<<<(1 << K15_) / 256, 256>>>(H);

    // 2) sign patterns -> per-pair scaled offsets
    size_t sm1 = (size_t)(32 * XSTR + C_ * D_ * 16 + C_ * K15_) * sizeof(float);
    cudaFuncSetAttribute(idx_kernel, cudaFuncAttributeMaxDynamicSharedMemorySize, (int)sm1);
    idx_kernel<<<(B + 31) / 32, 256, sm1>>>(x, S, T, B);

    // 3) paired fp16 LUT2, row-major 1 KB rows
    build_kernel<<<NROWS, 64>>>(LUT);

    // 4) broadcast-row tiled gather-sum
    cudaFuncSetAttribute(gather_kernel, cudaFuncAttributeMaxDynamicSharedMemorySize, GSMEM);
    dim3 gg(NJT, (B + GCHUNK - 1) / GCHUNK);
    gather_kernel<<<gg, 512, GSMEM>>>(out, B);
}

// round 8
// speedup vs baseline: 2.9345x; 1.0012x over previous
#include <cuda_runtime.h>
#include <cuda_fp16.h>
#include <cstdint>

// Problem constants (fixed shapes per reference)
#define C_    64
#define D_    8
#define K15_  15
#define K16_  16
#define OUTW  512
#define MAXB  32768
#define NPAIR 32            // C_/2
#define ROWB  144           // 128 B payload (64 j fp16) + 16 B pad (bank de-conflict)
#define TILEB (256 * ROWB)  // 36864 B: one (pair, jt) tile = 256 combo rows
#define NJT   8             // j-tiles of 64
#define GCH   512           // b per gather CTA

// Scratch (no cudaMalloc allowed): zero-initialized device globals.
__device__ uint8_t        g_table[1 << K15_];                // sign pattern -> argmax_j
__device__ unsigned short g_poff[MAXB * NPAIR];              // (b,p) -> e*144 (row byte off)
__device__ __align__(16) unsigned char g_lut2[NPAIR * NJT * TILEB];  // 9.4 MB paired LUT

__device__ __forceinline__ void cp16(uint32_t daddr, const void* src) {
    asm volatile("cp.async.cg.shared.global [%0], [%1], 16;" :: "r"(daddr), "l"(src) : "memory");
}

// ---------------------------------------------------------------------------
// Kernel T: precompute argmax table (H staged in smem).
// ---------------------------------------------------------------------------
__global__ void __launch_bounds__(256) table_kernel(const float* __restrict__ H) {
    __shared__ float Hs[K15_ * K16_];
    for (int i = threadIdx.x; i < K15_ * K16_; i += 256) Hs[i] = H[i];
    __syncthreads();
    int m = blockIdx.x * blockDim.x + threadIdx.x;
    if (m >= (1 << K15_)) return;
    float h[K16_];
#pragma unroll
    for (int j = 0; j < K16_; j++) h[j] = 0.f;
#pragma unroll
    for (int k = 0; k < K15_; k++) {
        float sgn = ((m >> k) & 1) ? 1.f : -1.f;
#pragma unroll
        for (int j = 0; j < K16_; j++) h[j] += sgn * Hs[k * K16_ + j];
    }
    float best = h[0];
    int   bi = 0;
#pragma unroll
    for (int j = 1; j < K16_; j++)
        if (h[j] > best) { best = h[j]; bi = j; }
    g_table[m] = (uint8_t)bi;
}

// ---------------------------------------------------------------------------
// Kernel P (fused): blocks [0, nidx) run the idx pass; blocks [nidx, nidx+2048)
// run the LUT2 build. Independent work, overlapped on the SMs.
// ---------------------------------------------------------------------------
#define XSTR 516
__global__ void __launch_bounds__(256) prep_kernel(const float* __restrict__ x,
                                                   const float* __restrict__ S,
                                                   const float* __restrict__ T,
                                                   const float* __restrict__ LUT,
                                                   int B, int nidx) {
    if ((int)blockIdx.x >= nidx) {
        // ---- build part: 4 combo rows per block, 64 threads per row ----
        const int row = ((int)blockIdx.x - nidx) * 4 + (threadIdx.x >> 6);
        const int t64 = threadIdx.x & 63;
        const int p = row >> 8, e = row & 255;
        const int r0 = p * 32 + (e >> 4);
        const int r1 = p * 32 + 16 + (e & 15);
        const int jt = t64 >> 3, seg = t64 & 7;
        const int j0 = jt * 64 + seg * 8;
        const float4* a = (const float4*)(LUT + (size_t)r0 * OUTW + j0);
        const float4* c = (const float4*)(LUT + (size_t)r1 * OUTW + j0);
        const float4 a0 = a[0], a1 = a[1], c0 = c[0], c1 = c[1];
        __half2 h0 = __floats2half2_rn(a0.x + c0.x, a0.y + c0.y);
        __half2 h1 = __floats2half2_rn(a0.z + c0.z, a0.w + c0.w);
        __half2 h2 = __floats2half2_rn(a1.x + c1.x, a1.y + c1.y);
        __half2 h3 = __floats2half2_rn(a1.z + c1.z, a1.w + c1.w);
        uint4 v;
        v.x = *(uint32_t*)&h0; v.y = *(uint32_t*)&h1;
        v.z = *(uint32_t*)&h2; v.w = *(uint32_t*)&h3;
        *(uint4*)(g_lut2 + ((size_t)(p * NJT + jt) * 256 + e) * ROWB + seg * 16) = v;
        return;
    }

    // ---- idx part: per (b,c) sign pattern -> argmax -> row byte offset ----
    extern __shared__ float sm[];
    float* x_s = sm;                         // 32 * 516
    float* S_s = sm + 32 * XSTR;             // [c][d][16]
    float* T_s = S_s + C_ * D_ * 16;         // [c][15]

    const int tid = threadIdx.x;
    const int b0 = blockIdx.x * 32;

    for (int i = tid; i < 32 * 128; i += 256) {
        int bl = i >> 7, col4 = i & 127;
        float4 v = make_float4(0.f, 0.f, 0.f, 0.f);
        if (b0 + bl < B) v = ((const float4*)x)[(size_t)(b0 + bl) * 128 + col4];
        *(float4*)(x_s + bl * XSTR + col4 * 4) = v;
    }
    for (int i = tid; i < C_ * D_ * K15_; i += 256) {
        int cd = i / K15_, k = i - cd * K15_;
        S_s[cd * 16 + k] = S[i];
    }
    for (int i = tid; i < C_ * K15_; i += 256) T_s[i] = T[i];
    __syncthreads();

    const int warp = tid >> 5, lane = tid & 31;
    const int b = b0 + lane;

    int e8[8];
#pragma unroll
    for (int cc = 0; cc < 8; cc++) {
        const int c = warp * 8 + cc;
        const float4 xa = *(const float4*)(x_s + lane * XSTR + c * 8);
        const float4 xb = *(const float4*)(x_s + lane * XSTR + c * 8 + 4);
        float xr[D_] = {xa.x, xa.y, xa.z, xa.w, xb.x, xb.y, xb.z, xb.w};
        float acc[16];
#pragma unroll
        for (int k = 0; k < 16; k++) acc[k] = 0.f;
#pragma unroll
        for (int d = 0; d < D_; d++) {
            const float xd = xr[d];
            const float4* s4 = (const float4*)(S_s + (c * D_ + d) * 16);
            const float4 s0 = s4[0], s1 = s4[1], s2 = s4[2], s3 = s4[3];
            acc[0]  += xd * s0.x; acc[1]  += xd * s0.y; acc[2]  += xd * s0.z; acc[3]  += xd * s0.w;
            acc[4]  += xd * s1.x; acc[5]  += xd * s1.y; acc[6]  += xd * s1.z; acc[7]  += xd * s1.w;
            acc[8]  += xd * s2.x; acc[9]  += xd * s2.y; acc[10] += xd * s2.z; acc[11] += xd * s2.w;
            acc[12] += xd * s3.x; acc[13] += xd * s3.y; acc[14] += xd * s3.z;
        }
        unsigned m = 0;
#pragma unroll
        for (int k = 0; k < K15_; k++)
            if (acc[k] > T_s[c * K15_ + k]) m |= (1u << k);
        e8[cc] = g_table[m];
    }

    if (b < B) {
        ushort4 v;
        v.x = (unsigned short)((e8[0] * 16 + e8[1]) * ROWB);
        v.y = (unsigned short)((e8[2] * 16 + e8[3]) * ROWB);
        v.z = (unsigned short)((e8[4] * 16 + e8[5]) * ROWB);
        v.w = (unsigned short)((e8[6] * 16 + e8[7]) * ROWB);
        *(ushort4*)(g_poff + (size_t)b * NPAIR + 4 * warp) = v;
    }
}

// ---------------------------------------------------------------------------
// Kernel G (gather): out[b, jt*64 + l16*4 ..+4) = sum_p LUT2[p][row(b,p)][slice]
// 512 thr / 16 warps; warp owns 32 b, processed 2-per-iter: lanes 0-15 serve
// even-slot b, lanes 16-31 odd-slot b. Per iter: 1 broadcast LDS.U16 (row id)
// + 1 IADD + 1 LDS.64 (4 j) + 2 HADD2 into fp16 epoch accumulators; fp32 flush
// every 4 stages. 32 single-pair tiles (36 KB, stride-144 rows) double-buffered
// via cp.async. smem: ids 32 KB @0, buf0 @32768, buf1 @69632 (104 KB).
// ---------------------------------------------------------------------------
#define BUF0 32768u
#define BUF1 (32768u + TILEB)
#define GSMEM (BUF1 + TILEB)

__global__ void __launch_bounds__(512, 1) gather_kernel(float* __restrict__ out, int B) {
    extern __shared__ char smem[];
    const int tid = threadIdx.x, w = tid >> 5, lane = tid & 31;
    const int half = lane >> 4, l16 = lane & 15;
    const int jt = blockIdx.x;
    const int chunk = blockIdx.y * GCH;
    const uint32_t sb = (uint32_t)__cvta_generic_to_shared(smem);

    // prefetch stage 0 (pair 0)
    {
        const unsigned char* src = g_lut2 + (size_t)jt * TILEB;   // pair 0
        for (int k = tid; k < TILEB / 16; k += 512)
            cp16(sb + BUF0 + k * 16, src + k * 16);
        asm volatile("cp.async.commit_group;" ::: "memory");
    }

    // stage ids: 512 b x 64 B, contiguous
    {
        const uint4* src = (const uint4*)(g_poff + (size_t)chunk * NPAIR);
        uint4* dst = (uint4*)smem;
#pragma unroll
        for (int i = 0; i < 4; i++) dst[tid + i * 512] = src[tid + i * 512];
    }

    float4 acc[16];
#pragma unroll
    for (int i = 0; i < 16; i++) acc[i] = make_float4(0.f, 0.f, 0.f, 0.f);

    // id table base for this (warp, half): b = w*32 + 2*i + half
    const unsigned short* idp = (const unsigned short*)smem + (w * 32 + half) * NPAIR;

    for (int ep = 0; ep < 8; ep++) {
        __half2 h0[16], h1[16];
#pragma unroll
        for (int sub = 0; sub < 4; sub++) {
            const int s = ep * 4 + sub;
            const uint32_t bo = (s & 1) ? BUF1 : BUF0;
            if (s + 1 < NPAIR) {
                const uint32_t nbo = (s & 1) ? BUF0 : BUF1;
                const unsigned char* src = g_lut2 + (size_t)((s + 1) * NJT + jt) * TILEB;
                for (int k = tid; k < TILEB / 16; k += 512)
                    cp16(sb + nbo + k * 16, src + k * 16);
                asm volatile("cp.async.commit_group;" ::: "memory");
                asm volatile("cp.async.wait_group 1;" ::: "memory");
            } else {
                asm volatile("cp.async.wait_group 0;" ::: "memory");
            }
            __syncthreads();

            const char* bufp = smem + bo + l16 * 8;
#pragma unroll
            for (int i = 0; i < 16; i++) {
                const uint32_t id = idp[i * 64 + s];            // broadcast per half
                const uint2 v = *(const uint2*)(bufp + id);     // 4 j fp16
                const __half2 va = *(const __half2*)&v.x;
                const __half2 vb = *(const __half2*)&v.y;
                if (sub == 0) { h0[i] = va;               h1[i] = vb; }
                else          { h0[i] = __hadd2(h0[i], va); h1[i] = __hadd2(h1[i], vb); }
            }
            __syncthreads();   // all reads of 'bo' done before next prefetch overwrites it
        }
#pragma unroll
        for (int i = 0; i < 16; i++) {
            const float2 f0 = __half22float2(h0[i]);
            const float2 f1 = __half22float2(h1[i]);
            acc[i].x += f0.x; acc[i].y += f0.y;
            acc[i].z += f1.x; acc[i].w += f1.y;
        }
    }

#pragma unroll
    for (int i = 0; i < 16; i++) {
        const int b = chunk + w * 32 + 2 * i + half;
        if (b < B)
            *(float4*)(out + (size_t)b * OUTW + jt * 64 + l16 * 4) = acc[i];
    }
}

// ---------------------------------------------------------------------------
extern "C" void kernel_launch(void* const* d_in, const int* in_sizes, int n_in,
                              void* d_out, int out_size) {
    const float* x   = (const float*)d_in[0];
    const float* S   = (const float*)d_in[1];
    const float* H   = (const float*)d_in[2];
    const float* T   = (const float*)d_in[3];
    const float* LUT = (const float*)d_in[4];
    float*       out = (float*)d_out;

    const int B = in_sizes[0] / (C_ * D_);

    // 1) argmax table from H
    table_kernel<<<(1 << K15_) / 256, 256>>>(H);

    // 2) fused: sign-pattern indices + paired fp16 LUT2 build
    const int nidx = (B + 31) / 32;
    size_t sm1 = (size_t)(32 * XSTR + C_ * D_ * 16 + C_ * K15_) * sizeof(float);
    cudaFuncSetAttribute(prep_kernel, cudaFuncAttributeMaxDynamicSharedMemorySize, (int)sm1);
    prep_kernel<<<nidx + 2048, 256, sm1>>>(x, S, T, LUT, B, nidx);

    // 3) broadcast-row LDS.64 gather-sum
    cudaFuncSetAttribute(gather_kernel, cudaFuncAttributeMaxDynamicSharedMemorySize, GSMEM);
    dim3 gg(NJT, (B + GCH - 1) / GCH);
    gather_kernel<<<gg, 512, GSMEM>>>(out, B);
}

// round 10
// speedup vs baseline: 3.3338x; 1.1361x over previous
#include <cuda_runtime.h>
#include <cuda_fp16.h>
#include <cstdint>

// Problem constants (fixed shapes per reference)
#define C_    64
#define D_    8
#define K15_  15
#define K16_  16
#define OUTW  512
#define MAXB  32768
#define NJT   8             // j-tiles of 64
#define ROWB  128           // 64 j fp16 per row
#define TROWS 1024          // c*16+e rows per tile
#define TILEB (TROWS * ROWB)  // 131072 B: one jt tile, smem-resident
#define GCH   512           // b per gather CTA

// Scratch (no cudaMalloc allowed): zero-initialized device globals.
__device__ uint8_t        g_table[1 << K15_];               // sign pattern -> argmax_j
__device__ unsigned short g_poff[MAXB * C_];                // (b,c) -> e*128 (row byte off)
__device__ __align__(16) unsigned char g_lut1[NJT * TILEB]; // 1 MB: fp16 LUT, [jt][c*16+e][64 j]

__device__ __forceinline__ void cp16(uint32_t daddr, const void* src) {
    asm volatile("cp.async.cg.shared.global [%0], [%1], 16;" :: "r"(daddr), "l"(src) : "memory");
}

// ---------------------------------------------------------------------------
// Kernel T: precompute argmax table (H staged in smem).
// ---------------------------------------------------------------------------
__global__ void __launch_bounds__(256) table_kernel(const float* __restrict__ H) {
    __shared__ float Hs[K15_ * K16_];
    for (int i = threadIdx.x; i < K15_ * K16_; i += 256) Hs[i] = H[i];
    __syncthreads();
    int m = blockIdx.x * blockDim.x + threadIdx.x;
    if (m >= (1 << K15_)) return;
    float h[K16_];
#pragma unroll
    for (int j = 0; j < K16_; j++) h[j] = 0.f;
#pragma unroll
    for (int k = 0; k < K15_; k++) {
        float sgn = ((m >> k) & 1) ? 1.f : -1.f;
#pragma unroll
        for (int j = 0; j < K16_; j++) h[j] += sgn * Hs[k * K16_ + j];
    }
    float best = h[0];
    int   bi = 0;
#pragma unroll
    for (int j = 1; j < K16_; j++)
        if (h[j] > best) { best = h[j]; bi = j; }
    g_table[m] = (uint8_t)bi;
}

// ---------------------------------------------------------------------------
// Kernel P (fused): blocks [0, nidx) run the idx pass; blocks [nidx, nidx+256)
// reformat LUT -> fp16 tiled g_lut1. Independent work, overlapped on the SMs.
// ---------------------------------------------------------------------------
#define XSTR 516
__global__ void __launch_bounds__(256) prep_kernel(const float* __restrict__ x,
                                                   const float* __restrict__ S,
                                                   const float* __restrict__ T,
                                                   const float* __restrict__ LUT,
                                                   int B, int nidx) {
    if ((int)blockIdx.x >= nidx) {
        // ---- build part: 4 LUT rows per block, 64 threads per row ----
        const int row = ((int)blockIdx.x - nidx) * 4 + (threadIdx.x >> 6);  // c*16+e
        const int t64 = threadIdx.x & 63;
        const int jt = t64 >> 3, seg = t64 & 7;
        const float4* a = (const float4*)(LUT + (size_t)row * OUTW + jt * 64 + seg * 8);
        const float4 a0 = a[0], a1 = a[1];
        __half2 h0 = __floats2half2_rn(a0.x, a0.y);
        __half2 h1 = __floats2half2_rn(a0.z, a0.w);
        __half2 h2 = __floats2half2_rn(a1.x, a1.y);
        __half2 h3 = __floats2half2_rn(a1.z, a1.w);
        uint4 v;
        v.x = *(uint32_t*)&h0; v.y = *(uint32_t*)&h1;
        v.z = *(uint32_t*)&h2; v.w = *(uint32_t*)&h3;
        *(uint4*)(g_lut1 + ((size_t)jt * TROWS + row) * ROWB + seg * 16) = v;
        return;
    }

    // ---- idx part: per (b,c) sign pattern -> argmax -> row byte offset ----
    extern __shared__ float sm[];
    float* x_s = sm;                         // 32 * 516
    float* S_s = sm + 32 * XSTR;             // [c][d][16]
    float* T_s = S_s + C_ * D_ * 16;         // [c][15]

    const int tid = threadIdx.x;
    const int b0 = blockIdx.x * 32;

    for (int i = tid; i < 32 * 128; i += 256) {
        int bl = i >> 7, col4 = i & 127;
        float4 v = make_float4(0.f, 0.f, 0.f, 0.f);
        if (b0 + bl < B) v = ((const float4*)x)[(size_t)(b0 + bl) * 128 + col4];
        *(float4*)(x_s + bl * XSTR + col4 * 4) = v;
    }
    for (int i = tid; i < C_ * D_ * K15_; i += 256) {
        int cd = i / K15_, k = i - cd * K15_;
        S_s[cd * 16 + k] = S[i];
    }
    for (int i = tid; i < C_ * K15_; i += 256) T_s[i] = T[i];
    __syncthreads();

    const int warp = tid >> 5, lane = tid & 31;
    const int b = b0 + lane;

    int e8[8];
#pragma unroll
    for (int cc = 0; cc < 8; cc++) {
        const int c = warp * 8 + cc;
        const float4 xa = *(const float4*)(x_s + lane * XSTR + c * 8);
        const float4 xb = *(const float4*)(x_s + lane * XSTR + c * 8 + 4);
        float xr[D_] = {xa.x, xa.y, xa.z, xa.w, xb.x, xb.y, xb.z, xb.w};
        float acc[16];
#pragma unroll
        for (int k = 0; k < 16; k++) acc[k] = 0.f;
#pragma unroll
        for (int d = 0; d < D_; d++) {
            const float xd = xr[d];
            const float4* s4 = (const float4*)(S_s + (c * D_ + d) * 16);
            const float4 s0 = s4[0], s1 = s4[1], s2 = s4[2], s3 = s4[3];
            acc[0]  += xd * s0.x; acc[1]  += xd * s0.y; acc[2]  += xd * s0.z; acc[3]  += xd * s0.w;
            acc[4]  += xd * s1.x; acc[5]  += xd * s1.y; acc[6]  += xd * s1.z; acc[7]  += xd * s1.w;
            acc[8]  += xd * s2.x; acc[9]  += xd * s2.y; acc[10] += xd * s2.z; acc[11] += xd * s2.w;
            acc[12] += xd * s3.x; acc[13] += xd * s3.y; acc[14] += xd * s3.z;
        }
        unsigned m = 0;
#pragma unroll
        for (int k = 0; k < K15_; k++)
            if (acc[k] > T_s[c * K15_ + k]) m |= (1u << k);
        e8[cc] = g_table[m];
    }

    if (b < B) {
        // c = warp*8 + cc ; store 8 u16 byte-offsets e*128 (<= 32640, fits u16)
        ushort4 v0, v1;
        v0.x = (unsigned short)(e8[0] << 7); v0.y = (unsigned short)(e8[1] << 7);
        v0.z = (unsigned short)(e8[2] << 7); v0.w = (unsigned short)(e8[3] << 7);
        v1.x = (unsigned short)(e8[4] << 7); v1.y = (unsigned short)(e8[5] << 7);
        v1.z = (unsigned short)(e8[6] << 7); v1.w = (unsigned short)(e8[7] << 7);
        uint4 pk;
        pk.x = (uint32_t)v0.x | ((uint32_t)v0.y << 16);
        pk.y = (uint32_t)v0.z | ((uint32_t)v0.w << 16);
        pk.z = (uint32_t)v1.x | ((uint32_t)v1.y << 16);
        pk.w = (uint32_t)v1.z | ((uint32_t)v1.w << 16);
        *(uint4*)(g_poff + (size_t)b * C_ + warp * 8) = pk;
    }
}

// ---------------------------------------------------------------------------
// Kernel G (gather): out[b, jt*64 + l16*4 ..+4) = sum_c LUT1[jt][c*16+e(b,c)][slice]
// 1024 thr / 32 warps; warp owns 16 b, half-split (lanes 0-15 even slot, 16-31
// odd). Whole jt tile (128 KB) + ids (64 KB) smem-resident: ONE sync, then a
// pure gather loop. Per 4 c: broadcast LDS.64 of 4 packed ids + 4 LDS.64 row
// gathers + 4-term fp16 tree + fp32 flush. No streaming, no stage syncs.
// ---------------------------------------------------------------------------
#define IDS_B (GCH * 128)             // 65536
#define GSMEM (IDS_B + TILEB)         // 196608

__global__ void __launch_bounds__(1024, 1) gather_kernel(float* __restrict__ out, int B) {
    extern __shared__ char smem[];
    const int tid = threadIdx.x, w = tid >> 5, lane = tid & 31;
    const int half = lane >> 4, l16 = lane & 15;
    const int jt = blockIdx.x;
    const int chunk = blockIdx.y * GCH;
    const uint32_t sb = (uint32_t)__cvta_generic_to_shared(smem);

    // ---- load ids (512 b x 128 B) and the whole jt tile (128 KB), one wait
    {
        const unsigned char* ip = (const unsigned char*)g_poff + (size_t)chunk * 128;
#pragma unroll
        for (int k = 0; k < 4; k++)
            cp16(sb + (tid + k * 1024) * 16, ip + (tid + k * 1024) * 16);
        const unsigned char* tp = g_lut1 + (size_t)jt * TILEB;
#pragma unroll
        for (int k = 0; k < 8; k++)
            cp16(sb + IDS_B + (tid + k * 1024) * 16, tp + (tid + k * 1024) * 16);
        asm volatile("cp.async.commit_group;" ::: "memory");
        asm volatile("cp.async.wait_group 0;" ::: "memory");
    }
    __syncthreads();

    const char* tile = smem + IDS_B + l16 * 8;   // lane's 8B j-slice within each row

#pragma unroll
    for (int i = 0; i < 8; i++) {
        const int bl = w * 16 + 2 * i + half;                 // b slot in chunk
        const uint2* idp = (const uint2*)(smem + bl * 128);   // 64 u16 ids, 16 uint2
        float4 a = make_float4(0.f, 0.f, 0.f, 0.f);
#pragma unroll
        for (int c4 = 0; c4 < 16; c4++) {
            const uint2 id4 = idp[c4];                        // broadcast LDS.64 (per half)
            const char* p0 = tile + (id4.x & 0xFFFFu);
            const char* p1 = tile + (id4.x >> 16);
            const char* p2 = tile + (id4.y & 0xFFFFu);
            const char* p3 = tile + (id4.y >> 16);
            const uint2 v0 = *(const uint2*)(p0 + (4 * c4 + 0) * 2048);
            const uint2 v1 = *(const uint2*)(p1 + (4 * c4 + 1) * 2048);
            const uint2 v2 = *(const uint2*)(p2 + (4 * c4 + 2) * 2048);
            const uint2 v3 = *(const uint2*)(p3 + (4 * c4 + 3) * 2048);
            // 4-term fp16 trees (lo pair of j, hi pair of j), then fp32 flush
            __half2 s0 = __hadd2(__hadd2(*(const __half2*)&v0.x, *(const __half2*)&v1.x),
                                 __hadd2(*(const __half2*)&v2.x, *(const __half2*)&v3.x));
            __half2 s1 = __hadd2(__hadd2(*(const __half2*)&v0.y, *(const __half2*)&v1.y),
                                 __hadd2(*(const __half2*)&v2.y, *(const __half2*)&v3.y));
            const float2 f0 = __half22float2(s0);
            const float2 f1 = __half22float2(s1);
            a.x += f0.x; a.y += f0.y; a.z += f1.x; a.w += f1.y;
        }
        const int b = chunk + bl;
        if (b < B)
            *(float4*)(out + (size_t)b * OUTW + jt * 64 + l16 * 4) = a;
    }
}

// ---------------------------------------------------------------------------
extern "C" void kernel_launch(void* const* d_in, const int* in_sizes, int n_in,
                              void* d_out, int out_size) {
    const float* x   = (const float*)d_in[0];
    const float* S   = (const float*)d_in[1];
    const float* H   = (const float*)d_in[2];
    const float* T   = (const float*)d_in[3];
    const float* LUT = (const float*)d_in[4];
    float*       out = (float*)d_out;

    const int B = in_sizes[0] / (C_ * D_);

    // 1) argmax table from H
    table_kernel<<<(1 << K15_) / 256, 256>>>(H);

    // 2) fused: sign-pattern indices + fp16 tiled LUT reformat
    const int nidx = (B + 31) / 32;
    size_t sm1 = (size_t)(32 * XSTR + C_ * D_ * 16 + C_ * K15_) * sizeof(float);
    cudaFuncSetAttribute(prep_kernel, cudaFuncAttributeMaxDynamicSharedMemorySize, (int)sm1);
    prep_kernel<<<nidx + 256, 256, sm1>>>(x, S, T, LUT, B, nidx);

    // 3) smem-resident tile gather-sum (no streaming)
    cudaFuncSetAttribute(gather_kernel, cudaFuncAttributeMaxDynamicSharedMemorySize, GSMEM);
    dim3 gg(NJT, (B + GCH - 1) / GCH);
    gather_kernel<<<gg, 1024, GSMEM>>>(out, B);
}

// round 11
// speedup vs baseline: 3.9597x; 1.1877x over previous
#include <cuda_runtime.h>
#include <cuda_fp16.h>
#include <cstdint>

// Problem constants (fixed shapes per reference)
#define C_    64
#define D_    8
#define K15_  15
#define K16_  16
#define OUTW  512
#define MAXB  32768
#define NJT   8               // j-tiles of 64
#define ROWB  128             // 64 j fp16 per row
#define TROWS 1024            // c*16+e rows per tile
#define TILEB (TROWS * ROWB)  // 131072 B: one jt tile, smem-resident
#define GCH   256             // b per gather chunk
#define GY    18              // persistent CTAs per jt (8*18 = 144 ~ one wave)

// Scratch (no cudaMalloc allowed): zero-initialized device globals.
__device__ uint8_t        g_table[1 << K15_];               // sign pattern -> argmax_j
__device__ unsigned short g_poff[MAXB * C_];                // (b,c) -> e*128 (row byte off)
__device__ __align__(16) unsigned char g_lut1[NJT * TILEB]; // 1 MB: fp16 LUT, [jt][c*16+e][64 j]

__device__ __forceinline__ void cp16(uint32_t daddr, const void* src) {
    asm volatile("cp.async.cg.shared.global [%0], [%1], 16;" :: "r"(daddr), "l"(src) : "memory");
}

// ---------------------------------------------------------------------------
// Kernel T (fused): blocks [0,128) precompute the argmax table; blocks
// [128, 384) reformat LUT -> fp16 tiled g_lut1 (independent of the table).
// ---------------------------------------------------------------------------
__global__ void __launch_bounds__(256) table_kernel(const float* __restrict__ H,
                                                    const float* __restrict__ LUT) {
    if (blockIdx.x >= 128) {
        // ---- build part: 4 LUT rows per block, 64 threads per row ----
        const int row = ((int)blockIdx.x - 128) * 4 + (threadIdx.x >> 6);  // c*16+e
        const int t64 = threadIdx.x & 63;
        const int jt = t64 >> 3, seg = t64 & 7;
        const float4* a = (const float4*)(LUT + (size_t)row * OUTW + jt * 64 + seg * 8);
        const float4 a0 = a[0], a1 = a[1];
        __half2 h0 = __floats2half2_rn(a0.x, a0.y);
        __half2 h1 = __floats2half2_rn(a0.z, a0.w);
        __half2 h2 = __floats2half2_rn(a1.x, a1.y);
        __half2 h3 = __floats2half2_rn(a1.z, a1.w);
        uint4 v;
        v.x = *(uint32_t*)&h0; v.y = *(uint32_t*)&h1;
        v.z = *(uint32_t*)&h2; v.w = *(uint32_t*)&h3;
        *(uint4*)(g_lut1 + ((size_t)jt * TROWS + row) * ROWB + seg * 16) = v;
        return;
    }
    __shared__ float Hs[K15_ * K16_];
    for (int i = threadIdx.x; i < K15_ * K16_; i += 256) Hs[i] = H[i];
    __syncthreads();
    int m = blockIdx.x * blockDim.x + threadIdx.x;
    float h[K16_];
#pragma unroll
    for (int j = 0; j < K16_; j++) h[j] = 0.f;
#pragma unroll
    for (int k = 0; k < K15_; k++) {
        float sgn = ((m >> k) & 1) ? 1.f : -1.f;
#pragma unroll
        for (int j = 0; j < K16_; j++) h[j] += sgn * Hs[k * K16_ + j];
    }
    float best = h[0];
    int   bi = 0;
#pragma unroll
    for (int j = 1; j < K16_; j++)
        if (h[j] > best) { best = h[j]; bi = j; }
    g_table[m] = (uint8_t)bi;
}

// ---------------------------------------------------------------------------
// Kernel P (idx): per (b,c) sign pattern -> argmax -> row byte offset.
// x read DIRECTLY from gmem (32B sector-aligned per (b,c), each sector read
// exactly once chip-wide) — no x smem staging, no stage barrier; smem 37 KB
// (S padded [c][d][16] + T), so 3+ CTAs/SM.
// ---------------------------------------------------------------------------
__global__ void __launch_bounds__(256) idx_kernel(const float* __restrict__ x,
                                                  const float* __restrict__ S,
                                                  const float* __restrict__ T,
                                                  int B) {
    __shared__ float S_s[C_ * D_ * 16];
    __shared__ float T_s[C_ * K15_];

    const int tid = threadIdx.x;
    for (int i = tid; i < C_ * D_ * K15_; i += 256) {
        int cd = i / K15_, k = i - cd * K15_;
        S_s[cd * 16 + k] = S[i];
    }
    for (int i = tid; i < C_ * K15_; i += 256) T_s[i] = T[i];
    __syncthreads();

    const int warp = tid >> 5, lane = tid & 31;
    const int b = blockIdx.x * 32 + lane;
    const float* xrow = x + (size_t)((b < B) ? b : 0) * 512;

    int e8[8];
#pragma unroll
    for (int cc = 0; cc < 8; cc++) {
        const int c = warp * 8 + cc;
        const float4 xa = __ldg((const float4*)(xrow + c * 8));
        const float4 xb = __ldg((const float4*)(xrow + c * 8 + 4));
        float xr[D_] = {xa.x, xa.y, xa.z, xa.w, xb.x, xb.y, xb.z, xb.w};
        float acc[16];
#pragma unroll
        for (int k = 0; k < 16; k++) acc[k] = 0.f;
#pragma unroll
        for (int d = 0; d < D_; d++) {
            const float xd = xr[d];
            const float4* s4 = (const float4*)(S_s + (c * D_ + d) * 16);
            const float4 s0 = s4[0], s1 = s4[1], s2 = s4[2], s3 = s4[3];
            acc[0]  += xd * s0.x; acc[1]  += xd * s0.y; acc[2]  += xd * s0.z; acc[3]  += xd * s0.w;
            acc[4]  += xd * s1.x; acc[5]  += xd * s1.y; acc[6]  += xd * s1.z; acc[7]  += xd * s1.w;
            acc[8]  += xd * s2.x; acc[9]  += xd * s2.y; acc[10] += xd * s2.z; acc[11] += xd * s2.w;
            acc[12] += xd * s3.x; acc[13] += xd * s3.y; acc[14] += xd * s3.z;
        }
        unsigned m = 0;
#pragma unroll
        for (int k = 0; k < K15_; k++)
            if (acc[k] > T_s[c * K15_ + k]) m |= (1u << k);
        e8[cc] = g_table[m];
    }

    if (b < B) {
        uint4 pk;
        pk.x = (uint32_t)(e8[0] << 7) | ((uint32_t)(e8[1] << 7) << 16);
        pk.y = (uint32_t)(e8[2] << 7) | ((uint32_t)(e8[3] << 7) << 16);
        pk.z = (uint32_t)(e8[4] << 7) | ((uint32_t)(e8[5] << 7) << 16);
        pk.w = (uint32_t)(e8[6] << 7) | ((uint32_t)(e8[7] << 7) << 16);
        *(uint4*)(g_poff + (size_t)b * C_ + warp * 8) = pk;
    }
}

// ---------------------------------------------------------------------------
// Kernel G (gather, persistent): out[b, jt*64+l16*4..+4) = sum_c tile[c*16+e][slice]
// Grid 8 x GY = 144 CTAs (~one wave), 1024 thr. Each CTA loads its 128 KB jt
// tile ONCE, then loops over b-chunks of 256 with double-buffered cp.async id
// streaming (1 barrier per chunk). Warp owns 8 b (half-split); per (2b, 4c):
// broadcast LDS.64 of 4 packed ids + 4 LDS.64 row gathers (2 phases = 128 B/cyc,
// crossbar optimal) + 4-term fp16 tree + fp32 flush.
// smem: ids buf0 @0 (32 KB), buf1 @32768, tile @65536 (128 KB) = 192 KB.
// ---------------------------------------------------------------------------
#define IDB0 0u
#define IDB1 32768u
#define TOFF 65536u
#define GSMEM (TOFF + TILEB)

__global__ void __launch_bounds__(1024, 1) gather_kernel(float* __restrict__ out, int B) {
    extern __shared__ char smem[];
    const int tid = threadIdx.x, w = tid >> 5, lane = tid & 31;
    const int half = lane >> 4, l16 = lane & 15;
    const int jt = blockIdx.x;
    const uint32_t sb = (uint32_t)__cvta_generic_to_shared(smem);
    const int nch = (B + GCH - 1) / GCH;

    // ---- prologue: tile (once) + ids for first chunk
    {
        const unsigned char* tp = g_lut1 + (size_t)jt * TILEB;
#pragma unroll
        for (int k = 0; k < 8; k++)
            cp16(sb + TOFF + (tid + k * 1024) * 16, tp + (tid + k * 1024) * 16);
        const unsigned char* ip = (const unsigned char*)g_poff + (size_t)blockIdx.y * GCH * 128;
        cp16(sb + IDB0 + tid * 16, ip + tid * 16);
        cp16(sb + IDB0 + (tid + 1024) * 16, ip + (tid + 1024) * 16);
        asm volatile("cp.async.commit_group;" ::: "memory");
        asm volatile("cp.async.wait_group 0;" ::: "memory");
    }
    __syncthreads();

    const char* tile = smem + TOFF + l16 * 8;   // lane's 8B j-slice within each row

    int ch = blockIdx.y;
    uint32_t bufo = IDB0;
    while (ch < nch) {
        const int nx = ch + GY;
        if (nx < nch) {   // prefetch next chunk's ids into the other buffer
            const uint32_t nbo = bufo ^ IDB1;
            const unsigned char* ip = (const unsigned char*)g_poff + (size_t)nx * GCH * 128;
            cp16(sb + nbo + tid * 16, ip + tid * 16);
            cp16(sb + nbo + (tid + 1024) * 16, ip + (tid + 1024) * 16);
            asm volatile("cp.async.commit_group;" ::: "memory");
        }

        const int bbase = ch * GCH;
#pragma unroll
        for (int i = 0; i < 4; i++) {
            const int bl = w * 8 + 2 * i + half;                     // slot in chunk
            const uint2* idp = (const uint2*)(smem + bufo + bl * 128);
            float4 a = make_float4(0.f, 0.f, 0.f, 0.f);
#pragma unroll
            for (int c4 = 0; c4 < 16; c4++) {
                const uint2 id4 = idp[c4];                            // broadcast LDS.64 / half
                const char* p0 = tile + (id4.x & 0xFFFFu);
                const char* p1 = tile + (id4.x >> 16);
                const char* p2 = tile + (id4.y & 0xFFFFu);
                const char* p3 = tile + (id4.y >> 16);
                const uint2 v0 = *(const uint2*)(p0 + (4 * c4 + 0) * 2048);
                const uint2 v1 = *(const uint2*)(p1 + (4 * c4 + 1) * 2048);
                const uint2 v2 = *(const uint2*)(p2 + (4 * c4 + 2) * 2048);
                const uint2 v3 = *(const uint2*)(p3 + (4 * c4 + 3) * 2048);
                __half2 s0 = __hadd2(__hadd2(*(const __half2*)&v0.x, *(const __half2*)&v1.x),
                                     __hadd2(*(const __half2*)&v2.x, *(const __half2*)&v3.x));
                __half2 s1 = __hadd2(__hadd2(*(const __half2*)&v0.y, *(const __half2*)&v1.y),
                                     __hadd2(*(const __half2*)&v2.y, *(const __half2*)&v3.y));
                const float2 f0 = __half22float2(s0);
                const float2 f1 = __half22float2(s1);
                a.x += f0.x; a.y += f0.y; a.z += f1.x; a.w += f1.y;
            }
            const int b = bbase + bl;
            if (b < B)
                *(float4*)(out + (size_t)b * OUTW + jt * 64 + l16 * 4) = a;
        }

        if (nx >= nch) break;
        asm volatile("cp.async.wait_group 0;" ::: "memory");
        __syncthreads();                 // all warps done with old buffer + new ids visible
        bufo ^= IDB1;
        ch = nx;
    }
}

// ---------------------------------------------------------------------------
extern "C" void kernel_launch(void* const* d_in, const int* in_sizes, int n_in,
                              void* d_out, int out_size) {
    const float* x   = (const float*)d_in[0];
    const float* S   = (const float*)d_in[1];
    const float* H   = (const float*)d_in[2];
    const float* T   = (const float*)d_in[3];
    const float* LUT = (const float*)d_in[4];
    float*       out = (float*)d_out;

    const int B = in_sizes[0] / (C_ * D_);

    // 1) argmax table from H  +  fp16 tiled LUT reformat (independent halves)
    table_kernel<<<128 + 256, 256>>>(H, LUT);

    // 2) sign-pattern indices (direct-LDG x, small smem)
    idx_kernel<<<(B + 31) / 32, 256>>>(x, S, T, B);

    // 3) persistent smem-resident tile gather-sum with streamed ids
    cudaFuncSetAttribute(gather_kernel, cudaFuncAttributeMaxDynamicSharedMemorySize, GSMEM);
    dim3 gg(NJT, GY);
    gather_kernel<<<gg, 1024, GSMEM>>>(out, B);
}

// round 13
// speedup vs baseline: 4.2361x; 1.0698x over previous
#include <cuda_runtime.h>
#include <cuda_fp16.h>
#include <cstdint>

// Problem constants (fixed shapes per reference)
#define C_    64
#define D_    8
#define K15_  15
#define K16_  16
#define OUTW  512
#define MAXB  32768
#define NJT   8               // j-tiles of 64
#define ROWB  128             // 64 j fp16 per row
#define TROWS 1024            // c*16+e rows per tile
#define TILEB (TROWS * ROWB)  // 131072 B: one jt tile, smem-resident
#define GCH   128             // b per gather chunk (finer for balance)
#define GY    18              // persistent CTAs per jt (8*18 = 144 ~ one wave)

// Scratch (no cudaMalloc allowed): zero-initialized device globals.
__device__ uint8_t        g_table[1 << K15_];               // sign pattern -> argmax_j
__device__ unsigned short g_poff[MAXB * C_];                // (b,c) -> e*128 (row byte off)
__device__ __align__(16) unsigned char g_lut1[NJT * TILEB]; // 1 MB: fp16 LUT, [jt][c*16+e][64 j]

__device__ __forceinline__ void cp16(uint32_t daddr, const void* src) {
    asm volatile("cp.async.cg.shared.global [%0], [%1], 16;" :: "r"(daddr), "l"(src) : "memory");
}

// ---------------------------------------------------------------------------
// Kernel T (fused): blocks [0,128) precompute the argmax table; blocks
// [128, 384) reformat LUT -> fp16 tiled g_lut1 (independent of the table).
// ---------------------------------------------------------------------------
__global__ void __launch_bounds__(256) table_kernel(const float* __restrict__ H,
                                                    const float* __restrict__ LUT) {
    if (blockIdx.x >= 128) {
        const int row = ((int)blockIdx.x - 128) * 4 + (threadIdx.x >> 6);  // c*16+e
        const int t64 = threadIdx.x & 63;
        const int jt = t64 >> 3, seg = t64 & 7;
        const float4* a = (const float4*)(LUT + (size_t)row * OUTW + jt * 64 + seg * 8);
        const float4 a0 = a[0], a1 = a[1];
        __half2 h0 = __floats2half2_rn(a0.x, a0.y);
        __half2 h1 = __floats2half2_rn(a0.z, a0.w);
        __half2 h2 = __floats2half2_rn(a1.x, a1.y);
        __half2 h3 = __floats2half2_rn(a1.z, a1.w);
        uint4 v;
        v.x = *(uint32_t*)&h0; v.y = *(uint32_t*)&h1;
        v.z = *(uint32_t*)&h2; v.w = *(uint32_t*)&h3;
        *(uint4*)(g_lut1 + ((size_t)jt * TROWS + row) * ROWB + seg * 16) = v;
        return;
    }
    __shared__ float Hs[K15_ * K16_];
    for (int i = threadIdx.x; i < K15_ * K16_; i += 256) Hs[i] = H[i];
    __syncthreads();
    int m = blockIdx.x * blockDim.x + threadIdx.x;
    float h[K16_];
#pragma unroll
    for (int j = 0; j < K16_; j++) h[j] = 0.f;
#pragma unroll
    for (int k = 0; k < K15_; k++) {
        float sgn = ((m >> k) & 1) ? 1.f : -1.f;
#pragma unroll
        for (int j = 0; j < K16_; j++) h[j] += sgn * Hs[k * K16_ + j];
    }
    float best = h[0];
    int   bi = 0;
#pragma unroll
    for (int j = 1; j < K16_; j++)
        if (h[j] > best) { best = h[j]; bi = j; }
    g_table[m] = (uint8_t)bi;
}

// ---------------------------------------------------------------------------
// Kernel P (idx): per (b,c) sign pattern -> argmax -> row byte offset.
// Direct-LDG x, small smem (S padded [c][d][16] + T), 3+ CTAs/SM.
// ---------------------------------------------------------------------------
__global__ void __launch_bounds__(256) idx_kernel(const float* __restrict__ x,
                                                  const float* __restrict__ S,
                                                  const float* __restrict__ T,
                                                  int B) {
    __shared__ float S_s[C_ * D_ * 16];
    __shared__ float T_s[C_ * K15_];

    const int tid = threadIdx.x;
    for (int i = tid; i < C_ * D_ * K15_; i += 256) {
        int cd = i / K15_, k = i - cd * K15_;
        S_s[cd * 16 + k] = S[i];
    }
    for (int i = tid; i < C_ * K15_; i += 256) T_s[i] = T[i];
    __syncthreads();

    const int warp = tid >> 5, lane = tid & 31;
    const int b = blockIdx.x * 32 + lane;
    const float* xrow = x + (size_t)((b < B) ? b : 0) * 512;

    int e8[8];
#pragma unroll
    for (int cc = 0; cc < 8; cc++) {
        const int c = warp * 8 + cc;
        const float4 xa = __ldg((const float4*)(xrow + c * 8));
        const float4 xb = __ldg((const float4*)(xrow + c * 8 + 4));
        float xr[D_] = {xa.x, xa.y, xa.z, xa.w, xb.x, xb.y, xb.z, xb.w};
        float acc[16];
#pragma unroll
        for (int k = 0; k < 16; k++) acc[k] = 0.f;
#pragma unroll
        for (int d = 0; d < D_; d++) {
            const float xd = xr[d];
            const float4* s4 = (const float4*)(S_s + (c * D_ + d) * 16);
            const float4 s0 = s4[0], s1 = s4[1], s2 = s4[2], s3 = s4[3];
            acc[0]  += xd * s0.x; acc[1]  += xd * s0.y; acc[2]  += xd * s0.z; acc[3]  += xd * s0.w;
            acc[4]  += xd * s1.x; acc[5]  += xd * s1.y; acc[6]  += xd * s1.z; acc[7]  += xd * s1.w;
            acc[8]  += xd * s2.x; acc[9]  += xd * s2.y; acc[10] += xd * s2.z; acc[11] += xd * s2.w;
            acc[12] += xd * s3.x; acc[13] += xd * s3.y; acc[14] += xd * s3.z;
        }
        unsigned m = 0;
#pragma unroll
        for (int k = 0; k < K15_; k++)
            if (acc[k] > T_s[c * K15_ + k]) m |= (1u << k);
        e8[cc] = g_table[m];
    }

    if (b < B) {
        uint4 pk;
        pk.x = (uint32_t)(e8[0] << 7) | ((uint32_t)(e8[1] << 7) << 16);
        pk.y = (uint32_t)(e8[2] << 7) | ((uint32_t)(e8[3] << 7) << 16);
        pk.z = (uint32_t)(e8[4] << 7) | ((uint32_t)(e8[5] << 7) << 16);
        pk.w = (uint32_t)(e8[6] << 7) | ((uint32_t)(e8[7] << 7) << 16);
        *(uint4*)(g_poff + (size_t)b * C_ + warp * 8) = pk;
    }
}

// ---------------------------------------------------------------------------
// Kernel G (gather, persistent): out[b, jt*64+l16*4..+4) = sum_c tile[c*16+e][slice]
// Grid 8 x GY = 144 CTAs, 1024 thr. Tile (128 KB) loaded once per CTA; id
// chunks (128 b x 128 B = 16 KB) double-buffered via cp.async.
// Warp owns 4 b per chunk (2 per iter, half-split). Per (2b, 8c): ONE uint4
// id LDS.128 (8 ids) + 8 LDS.64 row gathers + two 4-term fp16 trees per group
// of 4 c (numerics identical to R10/11) + fp32 flush.
// smem: ids buf0 @0 (16 KB), buf1 @16384, tile @32768 (128 KB) = 160 KB.
// ---------------------------------------------------------------------------
#define IDB0 0u
#define IDB1 16384u
#define TOFF 32768u
#define GSMEM (TOFF + TILEB)

__global__ void __launch_bounds__(1024, 1) gather_kernel(float* __restrict__ out, int B) {
    extern __shared__ char smem[];
    const int tid = threadIdx.x, w = tid >> 5, lane = tid & 31;
    const int half = lane >> 4, l16 = lane & 15;
    const int jt = blockIdx.x;
    const uint32_t sb = (uint32_t)__cvta_generic_to_shared(smem);
    const int nch = (B + GCH - 1) / GCH;

    // ---- prologue: tile (once) + ids for first chunk
    {
        const unsigned char* tp = g_lut1 + (size_t)jt * TILEB;
#pragma unroll
        for (int k = 0; k < 8; k++)
            cp16(sb + TOFF + (tid + k * 1024) * 16, tp + (tid + k * 1024) * 16);
        const unsigned char* ip = (const unsigned char*)g_poff + (size_t)blockIdx.y * GCH * 128;
        cp16(sb + IDB0 + tid * 16, ip + tid * 16);
        asm volatile("cp.async.commit_group;" ::: "memory");
        asm volatile("cp.async.wait_group 0;" ::: "memory");
    }
    __syncthreads();

    const char* tile = smem + TOFF + l16 * 8;   // lane's 8B j-slice within each row

    int ch = blockIdx.y;
    uint32_t bufo = IDB0;
    while (ch < nch) {
        const int nx = ch + GY;
        if (nx < nch) {   // prefetch next chunk's ids into the other buffer
            const uint32_t nbo = bufo ^ (IDB0 ^ IDB1);
            const unsigned char* ip = (const unsigned char*)g_poff + (size_t)nx * GCH * 128;
            cp16(sb + nbo + tid * 16, ip + tid * 16);
            asm volatile("cp.async.commit_group;" ::: "memory");
        }

        const int bbase = ch * GCH;
#pragma unroll
        for (int i = 0; i < 2; i++) {
            const int bl = w * 4 + 2 * i + half;                     // slot in chunk
            const uint4* idp = (const uint4*)(smem + bufo + bl * 128);  // 8 uint4 = 64 ids
            float4 a = make_float4(0.f, 0.f, 0.f, 0.f);
#pragma unroll
            for (int c8 = 0; c8 < 8; c8++) {
                const uint4 id8 = idp[c8];                            // LDS.128 broadcast / half
                const uint32_t o0 = id8.x & 0xFFFFu, o1 = id8.x >> 16;
                const uint32_t o2 = id8.y & 0xFFFFu, o3 = id8.y >> 16;
                const uint32_t o4 = id8.z & 0xFFFFu, o5 = id8.z >> 16;
                const uint32_t o6 = id8.w & 0xFFFFu, o7 = id8.w >> 16;
                const char* cb = tile + (size_t)(c8 * 8) * 2048;
                const uint2 v0 = *(const uint2*)(cb + o0 + 0 * 2048);
                const uint2 v1 = *(const uint2*)(cb + o1 + 1 * 2048);
                const uint2 v2 = *(const uint2*)(cb + o2 + 2 * 2048);
                const uint2 v3 = *(const uint2*)(cb + o3 + 3 * 2048);
                const uint2 v4 = *(const uint2*)(cb + o4 + 4 * 2048);
                const uint2 v5 = *(const uint2*)(cb + o5 + 5 * 2048);
                const uint2 v6 = *(const uint2*)(cb + o6 + 6 * 2048);
                const uint2 v7 = *(const uint2*)(cb + o7 + 7 * 2048);
                // group t=0..3 (numerics identical to previous 4-term trees)
                {
                    __half2 s0 = __hadd2(__hadd2(*(const __half2*)&v0.x, *(const __half2*)&v1.x),
                                         __hadd2(*(const __half2*)&v2.x, *(const __half2*)&v3.x));
                    __half2 s1 = __hadd2(__hadd2(*(const __half2*)&v0.y, *(const __half2*)&v1.y),
                                         __hadd2(*(const __half2*)&v2.y, *(const __half2*)&v3.y));
                    const float2 f0 = __half22float2(s0);
                    const float2 f1 = __half22float2(s1);
                    a.x += f0.x; a.y += f0.y; a.z += f1.x; a.w += f1.y;
                }
                // group t=4..7
                {
                    __half2 s0 = __hadd2(__hadd2(*(const __half2*)&v4.x, *(const __half2*)&v5.x),
                                         __hadd2(*(const __half2*)&v6.x, *(const __half2*)&v7.x));
                    __half2 s1 = __hadd2(__hadd2(*(const __half2*)&v4.y, *(const __half2*)&v5.y),
                                         __hadd2(*(const __half2*)&v6.y, *(const __half2*)&v7.y));
                    const float2 f0 = __half22float2(s0);
                    const float2 f1 = __half22float2(s1);
                    a.x += f0.x; a.y += f0.y; a.z += f1.x; a.w += f1.y;
                }
            }
            const int b = bbase + bl;
            if (b < B)
                *(float4*)(out + (size_t)b * OUTW + jt * 64 + l16 * 4) = a;
        }

        if (nx >= nch) break;
        asm volatile("cp.async.wait_group 0;" ::: "memory");
        __syncthreads();                 // old buffer drained + new ids visible
        bufo ^= (IDB0 ^ IDB1);
        ch = nx;
    }
}

// ---------------------------------------------------------------------------
extern "C" void kernel_launch(void* const* d_in, const int* in_sizes, int n_in,
                              void* d_out, int out_size) {
    const float* x   = (const float*)d_in[0];
    const float* S   = (const float*)d_in[1];
    const float* H   = (const float*)d_in[2];
    const float* T   = (const float*)d_in[3];
    const float* LUT = (const float*)d_in[4];
    float*       out = (float*)d_out;

    const int B = in_sizes[0] / (C_ * D_);

    // 1) argmax table from H  +  fp16 tiled LUT reformat (independent halves)
    table_kernel<<<128 + 256, 256>>>(H, LUT);

    // 2) sign-pattern indices (direct-LDG x, small smem)
    idx_kernel<<<(B + 31) / 32, 256>>>(x, S, T, B);

    // 3) persistent smem-resident tile gather-sum with streamed ids
    cudaFuncSetAttribute(gather_kernel, cudaFuncAttributeMaxDynamicSharedMemorySize, GSMEM);
    dim3 gg(NJT, GY);
    gather_kernel<<<gg, 1024, GSMEM>>>(out, B);
}